// round 11
// baseline (speedup 1.0000x reference)
#include <cuda_runtime.h>

// Problem constants (fixed shapes)
#define BB   2
#define HD   4
#define HH   128
#define WW   128
#define KS   7
#define KK   49
#define NSP  9
#define SS   64
#define PLANE (HH * WW)

typedef unsigned long long u64;

__device__ __forceinline__ u64 pk2(float lo, float hi) {
    u64 r; asm("mov.b64 %0, {%1, %2};" : "=l"(r) : "f"(lo), "f"(hi)); return r;
}
__device__ __forceinline__ void upk2(float& lo, float& hi, u64 v) {
    asm("mov.b64 {%0, %1}, %2;" : "=f"(lo), "=f"(hi) : "l"(v));
}
__device__ __forceinline__ u64 ffma2(u64 a, u64 b, u64 c) {
    u64 d; asm("fma.rn.f32x2 %0, %1, %2, %3;" : "=l"(d) : "l"(a), "l"(b), "l"(c)); return d;
}
__device__ __forceinline__ u64 fmul2(u64 a, u64 b) {
    u64 d; asm("mul.rn.f32x2 %0, %1, %2;" : "=l"(d) : "l"(a), "l"(b)); return d;
}

// Four pixels per warp: group g = lane>>3 handles pixel (h, w0+g).
// Pair-ownership: lane t owns k = 16j + 2t + par and k+1 (j = 0..2),
// par = g&1 (alignment parity of the pixel's 49-float block).
// Straggler k = par ? 0 : 48 owned by t==0.
// FMA passes run as packed fp32x2 (FFMA2); attn loads for ALL heads hoisted
// above the head loop so their latency overlaps the gather latency.
__global__ __launch_bounds__(128)
void attn_reweight_kernel(const float* __restrict__ attn,
                          const float* __restrict__ sims,
                          const int*   __restrict__ sinds,
                          float*       __restrict__ out)
{
    const int warpid = blockIdx.x * (blockDim.x >> 5) + (threadIdx.x >> 5);
    const int lane   = threadIdx.x & 31;
    const int g      = lane >> 3;
    const int t      = lane & 7;

    const int pix0 = warpid << 2;
    const int b    = pix0 >> 14;
    const int idx  = pix0 & 16383;
    const int h    = idx >> 7;
    const int w    = (idx & 127) + g;     // idx&127 multiple of 4
    const int par  = g & 1;

    const int hs = min(max(h - KS / 2, 0), HH - KS);
    const int ws = min(max(w - KS / 2, 0), WW - KS);

    int off[6];
#pragma unroll
    for (int r = 0; r < 6; ++r) {
        const int k = 16 * (r >> 1) + 2 * t + (r & 1) + par;
        off[r] = (hs + k / KS) * WW + ws + k % KS;
    }
    const int  ksg  = par ? 0 : 48;
    const int  offs = (hs + ksg / KS) * WW + ws + ksg % KS;
    const bool l0   = (t == 0);
    const float eps0 = l0 ? 1e-10f : 0.0f;

    const float* sb   = sims + b * (SS * PLANE);
    const int    offc = h * WW + w;

    const int sbase = (pix0 + g) * NSP;
    const int ind_a = __ldg(&sinds[sbase + t]);
    const int ind_b = l0 ? __ldg(&sinds[sbase + 8]) : 0;

    // ---- hoisted attn loads for ALL heads (overlap with gather below) ----
    const int base0      = (((b * HD) * HH + h) * WW + w) * KK;
    const int headStride = HH * WW * KK;
    float2 va[HD][3];
    float  vs[HD];
#pragma unroll
    for (int hd = 0; hd < HD; ++hd) {
        const float*  ab  = attn + base0 + hd * headStride;
        const float2* ab2 = (const float2*)(ab + par);
#pragma unroll
        for (int j = 0; j < 3; ++j)
            va[hd][j] = __ldg(&ab2[8 * j + t]);
        vs[hd] = l0 ? __ldg(ab + ksg) : -1e30f;
    }

    // ---- gather 9 planes (+ center pi) ----
    float ps[6][NSP], p6[NSP], pi[NSP];
#pragma unroll
    for (int sp = 0; sp < NSP; ++sp) {
        const int gid = (sp < 8) ? __shfl_sync(0xffffffffu, ind_a, (g << 3) + sp)
                                 : __shfl_sync(0xffffffffu, ind_b, (g << 3));
        const float* pl = sb + gid * PLANE;
#pragma unroll
        for (int r = 0; r < 6; ++r)
            ps[r][sp] = __ldg(&pl[off[r]]);
        p6[sp] = l0 ? __ldg(&pl[offs]) : 0.0f;
        pi[sp] = __ldg(&pl[offc]);
    }

    // pack p pairs once (amortized over 4 heads)
    u64 p2[3][NSP];
#pragma unroll
    for (int sp = 0; sp < NSP; ++sp) {
#pragma unroll
        for (int j = 0; j < 3; ++j)
            p2[j][sp] = pk2(ps[2 * j][sp], ps[2 * j + 1][sp]);
    }

    // ---- per-head compute ----
#pragma unroll
    for (int hd = 0; hd < HD; ++hd) {
        u64 a2[3];
#pragma unroll
        for (int j = 0; j < 3; ++j)
            a2[j] = pk2(__expf(va[hd][j].x), __expf(va[hd][j].y));
        const float a6 = __expf(vs[hd]);          // 0 on t!=0 (input -1e30)

        // d[sp] = eps + sum_k a_k p_sp[k]; packed partials, 8-lane butterfly
        float d[NSP];
#pragma unroll
        for (int sp = 0; sp < NSP; ++sp) {
            u64 acc2 = pk2(fmaf(a6, p6[sp], eps0), 0.0f);
            acc2 = ffma2(a2[0], p2[0][sp], acc2);
            acc2 = ffma2(a2[1], p2[1][sp], acc2);
            acc2 = ffma2(a2[2], p2[2][sp], acc2);
            float lo, hi; upk2(lo, hi, acc2);
            d[sp] = lo + hi;
        }
#pragma unroll
        for (int o = 4; o > 0; o >>= 1) {
#pragma unroll
            for (int sp = 0; sp < NSP; ++sp)
                d[sp] += __shfl_xor_sync(0xffffffffu, d[sp], o);
        }

        // w_sp = pi_sp / d_sp; paired reciprocals: 5 MUFU for 9 divides
        float wsp[NSP];
#pragma unroll
        for (int q = 0; q < 4; ++q) {
            const float prod = d[2 * q] * d[2 * q + 1];
            float rcp;
            asm("rcp.approx.f32 %0, %1;" : "=f"(rcp) : "f"(prod));
            wsp[2 * q]     = pi[2 * q]     * (rcp * d[2 * q + 1]);
            wsp[2 * q + 1] = pi[2 * q + 1] * (rcp * d[2 * q]);
        }
        {
            float r8;
            asm("rcp.approx.f32 %0, %1;" : "=f"(r8) : "f"(d[8]));
            wsp[8] = pi[8] * r8;
        }

        // out_k = a_k * sum_sp w_sp p_sp[k]  (packed)
        u64 o2[3] = {0ull, 0ull, 0ull};
        float o6 = 0.0f;
#pragma unroll
        for (int sp = 0; sp < NSP; ++sp) {
            const u64 w2 = pk2(wsp[sp], wsp[sp]);
            o2[0] = ffma2(w2, p2[0][sp], o2[0]);
            o2[1] = ffma2(w2, p2[1][sp], o2[1]);
            o2[2] = ffma2(w2, p2[2][sp], o2[2]);
            o6 = fmaf(wsp[sp], p6[sp], o6);
        }

        const int base = base0 + hd * headStride;
        float2* ob2 = (float2*)(out + base + par);
#pragma unroll
        for (int j = 0; j < 3; ++j) {
            const u64 r2 = fmul2(a2[j], o2[j]);
            float2 vv; upk2(vv.x, vv.y, r2);
            ob2[8 * j + t] = vv;                  // STG.64
        }
        if (l0) out[base + ksg] = a6 * o6;
    }
}

extern "C" void kernel_launch(void* const* d_in, const int* in_sizes, int n_in,
                              void* d_out, int out_size)
{
    const float* attn  = (const float*)d_in[0];
    const float* sims  = (const float*)d_in[1];
    const int*   sinds = (const int*)d_in[2];
    float*       out   = (float*)d_out;

    const int warps   = BB * HH * WW / 4;        // 8192 warps (4 pixels each)
    const int threads = 128;                     // 4 warps / CTA
    const int blocks  = warps / (threads / 32);  // 2048
    attn_reweight_kernel<<<blocks, threads>>>(attn, sims, sinds, out);
}

// round 12
// speedup vs baseline: 1.2323x; 1.2323x over previous
#include <cuda_runtime.h>

// Problem constants (fixed shapes)
#define BB   2
#define HD   4
#define HH   128
#define WW   128
#define KS   7
#define KK   49
#define NSP  9
#define SS   64
#define PLANE (HH * WW)

// Four pixels per warp: group g = lane>>3 handles pixel (h, w0+g).
// COLUMN ownership: lane t (=lane&7, t<7) owns window column t, i.e.
// k = 7r + t for r = 0..6. Lane 7 carries no data (eps seed only).
// Gather instruction r keeps each group's active lanes inside ONE window row
// (28 bytes -> ~1 cache line) -> minimal L1 wavefronts per instruction.
// Reductions: 8-lane xor butterfly. No max-subtraction (scale-invariant).
__global__ __launch_bounds__(128)
void attn_reweight_kernel(const float* __restrict__ attn,
                          const float* __restrict__ sims,
                          const int*   __restrict__ sinds,
                          float*       __restrict__ out)
{
    const int warpid = blockIdx.x * (blockDim.x >> 5) + (threadIdx.x >> 5);
    const int lane   = threadIdx.x & 31;
    const int g      = lane >> 3;
    const int t      = lane & 7;
    const bool act   = (t < 7);

    const int pix0 = warpid << 2;
    const int b    = pix0 >> 14;
    const int idx  = pix0 & 16383;
    const int h    = idx >> 7;
    const int w    = (idx & 127) + g;        // idx&127 multiple of 4

    const int hs = min(max(h - KS / 2, 0), HH - KS);
    const int ws = min(max(w - KS / 2, 0), WW - KS);

    // window offsets: value r of lane t is (row hs+r, col ws+t)
    const int wbase = hs * WW + ws + (act ? t : 6);   // lane 7: safe addr, unused
    const float eps0 = act ? 0.0f : 1e-10f;           // eps seed on lane 7

    const float* sb   = sims + b * (SS * PLANE);
    const int    offc = h * WW + w;                   // center (pi)

    // sinds: coalesced per-group loads, distribute via shfl
    const int sbase = (pix0 + g) * NSP;
    const int ind_a = __ldg(&sinds[sbase + t]);
    const int ind_b = (t == 0) ? __ldg(&sinds[sbase + 8]) : 0;

    // ---- gather 9 planes (+ center pi) ----
    float p[7][NSP], pi[NSP];
#pragma unroll
    for (int sp = 0; sp < NSP; ++sp) {
        const int gid = (sp < 8) ? __shfl_sync(0xffffffffu, ind_a, (g << 3) + sp)
                                 : __shfl_sync(0xffffffffu, ind_b, (g << 3));
        const float* pl = sb + gid * PLANE + wbase;
#pragma unroll
        for (int r = 0; r < 7; ++r)
            p[r][sp] = act ? __ldg(pl + r * WW) : 0.0f;
        pi[sp] = __ldg(&sb[gid * PLANE + offc]);      // broadcast within group
    }

    // ---- per-head compute ----
#pragma unroll
    for (int hd = 0; hd < HD; ++hd) {
        const int base = (((b * HD + hd) * HH + h) * WW + w) * KK;
        const float* ab = attn + base + t;            // k = 7r + t

        float a[7];
#pragma unroll
        for (int r = 0; r < 7; ++r)
            a[r] = __expf(act ? __ldg(ab + 7 * r) : -1e30f);   // 0 on lane 7

        // d[sp] = eps + sum_k a_k p_sp[k]; dual accumulators, 8-lane butterfly
        float d[NSP];
#pragma unroll
        for (int sp = 0; sp < NSP; ++sp) {
            float acc0 = fmaf(a[0], p[0][sp], eps0);
            float acc1 = a[1] * p[1][sp];
            acc0 = fmaf(a[2], p[2][sp], acc0);
            acc1 = fmaf(a[3], p[3][sp], acc1);
            acc0 = fmaf(a[4], p[4][sp], acc0);
            acc1 = fmaf(a[5], p[5][sp], acc1);
            acc0 = fmaf(a[6], p[6][sp], acc0);
            d[sp] = acc0 + acc1;
        }
#pragma unroll
        for (int o = 4; o > 0; o >>= 1) {
#pragma unroll
            for (int sp = 0; sp < NSP; ++sp)
                d[sp] += __shfl_xor_sync(0xffffffffu, d[sp], o);
        }

        // w_sp = pi_sp / d_sp; paired reciprocals: 5 MUFU for 9 divides
        float wsp[NSP];
#pragma unroll
        for (int q = 0; q < 4; ++q) {
            const float prod = d[2 * q] * d[2 * q + 1];
            float rcp;
            asm("rcp.approx.f32 %0, %1;" : "=f"(rcp) : "f"(prod));
            wsp[2 * q]     = pi[2 * q]     * (rcp * d[2 * q + 1]);
            wsp[2 * q + 1] = pi[2 * q + 1] * (rcp * d[2 * q]);
        }
        {
            float r8;
            asm("rcp.approx.f32 %0, %1;" : "=f"(r8) : "f"(d[8]));
            wsp[8] = pi[8] * r8;
        }

        // out_k = a_k * sum_sp w_sp p_sp[k]
        float o_[7];
#pragma unroll
        for (int r = 0; r < 7; ++r) o_[r] = 0.0f;
#pragma unroll
        for (int sp = 0; sp < NSP; ++sp) {
#pragma unroll
            for (int r = 0; r < 7; ++r)
                o_[r] = fmaf(wsp[sp], p[r][sp], o_[r]);
        }

        float* ob = out + base + t;
        if (act) {
#pragma unroll
            for (int r = 0; r < 7; ++r)
                ob[7 * r] = a[r] * o_[r];
        }
    }
}

extern "C" void kernel_launch(void* const* d_in, const int* in_sizes, int n_in,
                              void* d_out, int out_size)
{
    const float* attn  = (const float*)d_in[0];
    const float* sims  = (const float*)d_in[1];
    const int*   sinds = (const int*)d_in[2];
    float*       out   = (float*)d_out;

    const int warps   = BB * HH * WW / 4;        // 8192 warps (4 pixels each)
    const int threads = 128;                     // 4 warps / CTA
    const int blocks  = warps / (threads / 32);  // 2048
    attn_reweight_kernel<<<blocks, threads>>>(attn, sims, sinds, out);
}